// round 1
// baseline (speedup 1.0000x reference)
#include <cuda_runtime.h>
#include <math.h>

// Problem constants
#define B_  2
#define T_  512
#define H_  8
#define D_  64
#define E_  512
#define HD_ 512          // H_*D_
#define BH_ 16           // B_*H_
#define KK_ 64           // k_keep
#define M_  1024         // B_*T_

// ---------------- scratch (device globals; no allocation allowed) -----------
__device__ float g_Q [BH_ * T_ * D_];
__device__ float g_K0[BH_ * T_ * D_];
__device__ float g_K1[BH_ * T_ * D_];
__device__ float g_V0[BH_ * T_ * D_];
__device__ float g_V1[BH_ * T_ * D_];
__device__ float g_ctx[M_ * HD_];
__device__ int   g_idx0[BH_ * T_ * KK_];
__device__ int   g_idx1[BH_ * T_ * KK_];

// ---------------------------------------------------------------------------
// 1) Projection GEMMs: C = x @ W, written head-split  [bh][t][d]
//    grid: (N/64, M/64, 5)  block: 256
// ---------------------------------------------------------------------------
__global__ __launch_bounds__(256)
void proj_kernel(const float* __restrict__ x,
                 const float* __restrict__ Wq,
                 const float* __restrict__ Wk,
                 const float* __restrict__ Wv)
{
    const int z = blockIdx.z;
    const float* Bm = (z == 0) ? Wq
                    : (z <= 2) ? (Wk + (z - 1) * (E_ * HD_))
                               : (Wv + (z - 3) * (E_ * HD_));
    float* C = (z == 0) ? g_Q : (z == 1) ? g_K0 : (z == 2) ? g_K1
             : (z == 3) ? g_V0 : g_V1;

    const int n0 = blockIdx.x * 64;
    const int m0 = blockIdx.y * 64;
    const int tid = threadIdx.x;
    const int tx = tid & 15, ty = tid >> 4;

    __shared__ float As[64][16];      // [m][k]
    __shared__ float Bs[16][64];      // [k][n]

    float acc[4][4];
    #pragma unroll
    for (int i = 0; i < 4; i++)
        #pragma unroll
        for (int j = 0; j < 4; j++) acc[i][j] = 0.f;

    for (int k0 = 0; k0 < E_; k0 += 16) {
        #pragma unroll
        for (int i = tid; i < 64 * 16; i += 256) {
            int m = i >> 4, kk = i & 15;
            As[m][kk] = x[(m0 + m) * E_ + k0 + kk];
        }
        #pragma unroll
        for (int i = tid; i < 16 * 64; i += 256) {
            int kk = i >> 6, n = i & 63;
            Bs[kk][n] = Bm[(k0 + kk) * HD_ + n0 + n];
        }
        __syncthreads();
        #pragma unroll
        for (int kk = 0; kk < 16; kk++) {
            float ra[4], rb[4];
            #pragma unroll
            for (int i = 0; i < 4; i++) ra[i] = As[ty * 4 + i][kk];
            #pragma unroll
            for (int j = 0; j < 4; j++) rb[j] = Bs[kk][tx * 4 + j];
            #pragma unroll
            for (int i = 0; i < 4; i++)
                #pragma unroll
                for (int j = 0; j < 4; j++) acc[i][j] += ra[i] * rb[j];
        }
        __syncthreads();
    }

    #pragma unroll
    for (int i = 0; i < 4; i++) {
        int m = m0 + ty * 4 + i;
        int b = m >> 9, t = m & 511;
        #pragma unroll
        for (int j = 0; j < 4; j++) {
            int n = n0 + tx * 4 + j;
            int h = n >> 6, d = n & 63;
            C[(((b << 3) + h) * T_ + t) * D_ + d] = acc[i][j];
        }
    }
}

// ---------------------------------------------------------------------------
// 2) Causal top-64 per (b,h,t,r): dots + bitonic sort of packed keys.
//    grid: (T, BH, 2)  block: 256
// ---------------------------------------------------------------------------
__global__ __launch_bounds__(256)
void topk_kernel()
{
    const int t  = blockIdx.x;
    const int bh = blockIdx.y;
    const int r  = blockIdx.z;
    const float* Qv = g_Q + (bh * T_ + t) * D_;
    const float* K  = (r == 0 ? g_K0 : g_K1) + bh * T_ * D_;

    __shared__ unsigned long long keys[T_];

    const int tid  = threadIdx.x;
    const int lane = tid & 31;
    const int warp = tid >> 5;

    keys[tid]       = 0ull;
    keys[tid + 256] = 0ull;
    float q1 = Qv[lane];
    float q2 = Qv[lane + 32];
    __syncthreads();

    for (int s = warp; s <= t; s += 8) {
        const float* Kr = K + s * D_;
        float v = q1 * Kr[lane] + q2 * Kr[lane + 32];
        #pragma unroll
        for (int o = 16; o > 0; o >>= 1) v += __shfl_down_sync(0xffffffffu, v, o);
        if (lane == 0) {
            unsigned u = __float_as_uint(v);
            u ^= (u & 0x80000000u) ? 0xFFFFFFFFu : 0x80000000u;  // monotone fp32
            keys[s] = ((unsigned long long)u << 32) | (unsigned)(~(unsigned)s);
        }
    }
    __syncthreads();

    // bitonic sort, descending (value desc, index asc on ties)
    for (int k = 2; k <= T_; k <<= 1) {
        for (int j = k >> 1; j > 0; j >>= 1) {
            #pragma unroll
            for (int base = 0; base < T_; base += 256) {
                int i = base + tid;
                int ixj = i ^ j;
                if (ixj > i) {
                    bool up = ((i & k) != 0);          // inverted -> descending overall
                    unsigned long long a = keys[i], b = keys[ixj];
                    if ((a > b) == up) { keys[i] = b; keys[ixj] = a; }
                }
            }
            __syncthreads();
        }
    }

    if (tid < KK_) {
        int rank = min(tid, t);
        int s = (int)(~(unsigned)(keys[rank] & 0xFFFFFFFFull));
        int* dst = (r == 0 ? g_idx0 : g_idx1) + (bh * T_ + t) * KK_;
        dst[tid] = s;
    }
}

// ---------------------------------------------------------------------------
// 3) Order-3 attention per (b,h,t).  grid: (T, BH)  block: 256
//    dynamic smem: 3 x 64x65 f32 bufs + q + partials + 2 idx arrays
// ---------------------------------------------------------------------------
#define PAD 65
#define ATT_SMEM ((3 * 64 * PAD + 64 + 4 * 64) * 4 + 2 * 64 * 4)

__global__ __launch_bounds__(256)
void attn_kernel()
{
    extern __shared__ float sm[];
    float* buf1 = sm;                      // P0 -> later W
    float* buf2 = sm + 64 * PAD;           // K1g -> later V1g
    float* buf3 = sm + 2 * 64 * PAD;       // A / alpha
    float* qs   = sm + 3 * 64 * PAD;       // 64
    float* part = qs + 64;                 // 4*64
    int*   si0  = (int*)(part + 4 * 64);   // 64
    int*   si1  = si0 + 64;                // 64

    const int t  = blockIdx.x;
    const int bh = blockIdx.y;
    const int tid  = threadIdx.x;
    const int tx = tid & 15, ty = tid >> 4;
    const int lane = tid & 31, warp = tid >> 5;

    const float* K0b = g_K0 + bh * T_ * D_;
    const float* K1b = g_K1 + bh * T_ * D_;
    const float* V0b = g_V0 + bh * T_ * D_;
    const float* V1b = g_V1 + bh * T_ * D_;

    if (tid < 64) {
        qs[tid]  = g_Q[(bh * T_ + t) * D_ + tid];
        si0[tid] = g_idx0[(bh * T_ + t) * KK_ + tid];
        si1[tid] = g_idx1[(bh * T_ + t) * KK_ + tid];
    }
    __syncthreads();

    // P0[j][d] = q[d] * K0[idx0[j]][d] ; K1g[k][d]
    #pragma unroll
    for (int i = tid; i < 64 * 64; i += 256) {
        int j = i >> 6, d = i & 63;
        buf1[j * PAD + d] = qs[d] * K0b[si0[j] * D_ + d];
        buf2[j * PAD + d] = K1b[si1[j] * D_ + d];
    }
    __syncthreads();

    // A = P0 @ K1g^T  * scale
    {
        float acc[4][4];
        #pragma unroll
        for (int i = 0; i < 4; i++)
            #pragma unroll
            for (int j = 0; j < 4; j++) acc[i][j] = 0.f;
        #pragma unroll 8
        for (int d = 0; d < 64; d++) {
            float ra[4], rb[4];
            #pragma unroll
            for (int i = 0; i < 4; i++) ra[i] = buf1[(ty * 4 + i) * PAD + d];
            #pragma unroll
            for (int j = 0; j < 4; j++) rb[j] = buf2[(tx * 4 + j) * PAD + d];
            #pragma unroll
            for (int i = 0; i < 4; i++)
                #pragma unroll
                for (int j = 0; j < 4; j++) acc[i][j] += ra[i] * rb[j];
        }
        #pragma unroll
        for (int i = 0; i < 4; i++)
            #pragma unroll
            for (int j = 0; j < 4; j++)
                buf3[(ty * 4 + i) * PAD + tx * 4 + j] = acc[i][j] * 0.125f;
    }
    __syncthreads();

    // softmax over k (last axis), warp per row
    for (int row = warp; row < 64; row += 8) {
        float a1 = buf3[row * PAD + lane];
        float a2 = buf3[row * PAD + lane + 32];
        float m = fmaxf(a1, a2);
        #pragma unroll
        for (int o = 16; o > 0; o >>= 1) m = fmaxf(m, __shfl_xor_sync(0xffffffffu, m, o));
        float e1 = __expf(a1 - m), e2 = __expf(a2 - m);
        float s = e1 + e2;
        #pragma unroll
        for (int o = 16; o > 0; o >>= 1) s += __shfl_xor_sync(0xffffffffu, s, o);
        float inv = __frcp_rn(s);
        buf3[row * PAD + lane]      = e1 * inv;
        buf3[row * PAD + lane + 32] = e2 * inv;
    }
    __syncthreads();

    // load V1g into buf2 (K1g dead)
    #pragma unroll
    for (int i = tid; i < 64 * 64; i += 256) {
        int k = i >> 6, d = i & 63;
        buf2[k * PAD + d] = V1b[si1[k] * D_ + d];
    }
    __syncthreads();

    // W = alpha @ V1g  -> buf1 (P0 dead)
    {
        float acc[4][4];
        #pragma unroll
        for (int i = 0; i < 4; i++)
            #pragma unroll
            for (int j = 0; j < 4; j++) acc[i][j] = 0.f;
        #pragma unroll 8
        for (int k = 0; k < 64; k++) {
            float ra[4], rb[4];
            #pragma unroll
            for (int i = 0; i < 4; i++) ra[i] = buf3[(ty * 4 + i) * PAD + k];
            #pragma unroll
            for (int j = 0; j < 4; j++) rb[j] = buf2[k * PAD + tx * 4 + j];
            #pragma unroll
            for (int i = 0; i < 4; i++)
                #pragma unroll
                for (int j = 0; j < 4; j++) acc[i][j] += ra[i] * rb[j];
        }
        __syncthreads();   // all reads of buf1 (none) / buf3,buf2 done before overwrite of buf1
        #pragma unroll
        for (int i = 0; i < 4; i++)
            #pragma unroll
            for (int j = 0; j < 4; j++)
                buf1[(ty * 4 + i) * PAD + tx * 4 + j] = acc[i][j];
    }
    __syncthreads();

    // out[d] = sum_j W[j][d] * V0[idx0[j]][d]
    {
        int d = tid & 63;
        int jg = tid >> 6;             // 0..3
        float s = 0.f;
        #pragma unroll
        for (int jj = 0; jj < 16; jj++) {
            int j = jg * 16 + jj;
            s += buf1[j * PAD + d] * V0b[si0[j] * D_ + d];
        }
        part[jg * 64 + d] = s;
        __syncthreads();
        if (tid < 64) {
            float o = part[tid] + part[64 + tid] + part[128 + tid] + part[192 + tid];
            int b = bh >> 3, h = bh & 7;
            g_ctx[(b * T_ + t) * HD_ + h * D_ + tid] = o;
        }
    }
}

// ---------------------------------------------------------------------------
// 4) Output GEMM: out = ctx @ Wo   (plain row-major write)
//    grid: (8, 16)  block: 256
// ---------------------------------------------------------------------------
__global__ __launch_bounds__(256)
void out_kernel(const float* __restrict__ Wo, float* __restrict__ out)
{
    const int n0 = blockIdx.x * 64;
    const int m0 = blockIdx.y * 64;
    const int tid = threadIdx.x;
    const int tx = tid & 15, ty = tid >> 4;

    __shared__ float As[64][16];
    __shared__ float Bs[16][64];

    float acc[4][4];
    #pragma unroll
    for (int i = 0; i < 4; i++)
        #pragma unroll
        for (int j = 0; j < 4; j++) acc[i][j] = 0.f;

    for (int k0 = 0; k0 < HD_; k0 += 16) {
        #pragma unroll
        for (int i = tid; i < 64 * 16; i += 256) {
            int m = i >> 4, kk = i & 15;
            As[m][kk] = g_ctx[(m0 + m) * HD_ + k0 + kk];
        }
        #pragma unroll
        for (int i = tid; i < 16 * 64; i += 256) {
            int kk = i >> 6, n = i & 63;
            Bs[kk][n] = Wo[(k0 + kk) * E_ + n0 + n];
        }
        __syncthreads();
        #pragma unroll
        for (int kk = 0; kk < 16; kk++) {
            float ra[4], rb[4];
            #pragma unroll
            for (int i = 0; i < 4; i++) ra[i] = As[ty * 4 + i][kk];
            #pragma unroll
            for (int j = 0; j < 4; j++) rb[j] = Bs[kk][tx * 4 + j];
            #pragma unroll
            for (int i = 0; i < 4; i++)
                #pragma unroll
                for (int j = 0; j < 4; j++) acc[i][j] += ra[i] * rb[j];
        }
        __syncthreads();
    }
    #pragma unroll
    for (int i = 0; i < 4; i++)
        #pragma unroll
        for (int j = 0; j < 4; j++)
            out[(m0 + ty * 4 + i) * E_ + n0 + tx * 4 + j] = acc[i][j];
}

// ---------------------------------------------------------------------------
extern "C" void kernel_launch(void* const* d_in, const int* in_sizes, int n_in,
                              void* d_out, int out_size)
{
    const float* x  = (const float*)d_in[0];
    const float* Wq = (const float*)d_in[1];
    const float* Wk = (const float*)d_in[2];
    const float* Wv = (const float*)d_in[3];
    const float* Wo = (const float*)d_in[4];
    float* out = (float*)d_out;

    cudaFuncSetAttribute(attn_kernel,
                         cudaFuncAttributeMaxDynamicSharedMemorySize, ATT_SMEM);

    dim3 gProj(HD_ / 64, M_ / 64, 5);
    proj_kernel<<<gProj, 256>>>(x, Wq, Wk, Wv);

    dim3 gTop(T_, BH_, 2);
    topk_kernel<<<gTop, 256>>>();

    dim3 gAtt(T_, BH_);
    attn_kernel<<<gAtt, 256, ATT_SMEM>>>();

    dim3 gOut(E_ / 64, M_ / 64);
    out_kernel<<<gOut, 256>>>(Wo, out);
}

// round 2
// speedup vs baseline: 1.2861x; 1.2861x over previous
#include <cuda_runtime.h>
#include <math.h>

// Problem constants
#define B_  2
#define T_  512
#define H_  8
#define D_  64
#define E_  512
#define HD_ 512
#define BH_ 16
#define KK_ 64
#define M_  1024

typedef unsigned long long ull;

// ---------------- scratch ----------------
__device__ float g_Q [BH_ * T_ * D_];
__device__ float g_K0[BH_ * T_ * D_];
__device__ float g_K1[BH_ * T_ * D_];
__device__ float g_V0[BH_ * T_ * D_];
__device__ float g_V1[BH_ * T_ * D_];
__device__ float g_ctx[M_ * HD_];
__device__ int   g_idx0[BH_ * T_ * KK_];
__device__ int   g_idx1[BH_ * T_ * KK_];

// ---------------------------------------------------------------------------
// 1) Projections: C = x @ W for 5 weight matrices, head-split output.
//    64x64 tile, 64 threads, 8x8 microtile, BK=16.  grid (40,16)
// ---------------------------------------------------------------------------
__global__ __launch_bounds__(64)
void proj_kernel(const float* __restrict__ x,
                 const float* __restrict__ Wq,
                 const float* __restrict__ Wk,
                 const float* __restrict__ Wv)
{
    const int bx = blockIdx.x;            // 0..39 over concatenated N=2560
    const int z  = bx >> 3;               // which matrix
    const int nb = (bx & 7) * 64;         // n offset within matrix
    const int m0 = blockIdx.y * 64;

    const float* Bm = (z == 0) ? Wq
                    : (z <= 2) ? (Wk + (z - 1) * (E_ * HD_))
                               : (Wv + (z - 3) * (E_ * HD_));
    float* C = (z == 0) ? g_Q : (z == 1) ? g_K0 : (z == 2) ? g_K1
             : (z == 3) ? g_V0 : g_V1;

    const int tid = threadIdx.x;
    const int tx = tid & 7, ty = tid >> 3;

    __shared__ float As[16][64];   // [k][m]
    __shared__ float Bs[16][64];   // [k][n]

    float acc[8][8];
    #pragma unroll
    for (int i = 0; i < 8; i++)
        #pragma unroll
        for (int j = 0; j < 8; j++) acc[i][j] = 0.f;

    for (int k0 = 0; k0 < E_; k0 += 16) {
        // A: 64m x 16k, transpose on store. 256 float4 / 64 thr = 4 each.
        #pragma unroll
        for (int r = 0; r < 4; r++) {
            int idx = tid + r * 64;
            int m = idx >> 2, kp = (idx & 3) * 4;
            float4 v = *(const float4*)(x + (m0 + m) * E_ + k0 + kp);
            As[kp + 0][m] = v.x; As[kp + 1][m] = v.y;
            As[kp + 2][m] = v.z; As[kp + 3][m] = v.w;
        }
        // B: 16k x 64n direct. 256 float4 / 64 thr = 4 each.
        #pragma unroll
        for (int r = 0; r < 4; r++) {
            int idx = tid + r * 64;
            int row = idx >> 4, ch = (idx & 15) * 4;
            *(float4*)&Bs[row][ch] =
                *(const float4*)(Bm + (k0 + row) * HD_ + nb + ch);
        }
        __syncthreads();
        #pragma unroll
        for (int kk = 0; kk < 16; kk++) {
            float4 a0 = *(const float4*)&As[kk][ty * 8];
            float4 a1 = *(const float4*)&As[kk][ty * 8 + 4];
            float4 b0 = *(const float4*)&Bs[kk][tx * 8];
            float4 b1 = *(const float4*)&Bs[kk][tx * 8 + 4];
            float a[8] = {a0.x,a0.y,a0.z,a0.w,a1.x,a1.y,a1.z,a1.w};
            float b[8] = {b0.x,b0.y,b0.z,b0.w,b1.x,b1.y,b1.z,b1.w};
            #pragma unroll
            for (int i = 0; i < 8; i++)
                #pragma unroll
                for (int j = 0; j < 8; j++) acc[i][j] += a[i] * b[j];
        }
        __syncthreads();
    }

    const int h = bx & 7;                 // nb/64
    #pragma unroll
    for (int i = 0; i < 8; i++) {
        int m = m0 + ty * 8 + i;
        int b = m >> 9, t = m & 511;
        float* crow = C + (((b << 3) + h) * T_ + t) * D_ + tx * 8;
        #pragma unroll
        for (int j = 0; j < 8; j++) crow[j] = acc[i][j];
    }
}

// ---------------------------------------------------------------------------
// 2) Causal top-64: warp-register bitonic.  grid (T,BH,2), block 256
// ---------------------------------------------------------------------------
__device__ __forceinline__ void cex(ull &v, int i, int j, int k) {
    ull o = __shfl_xor_sync(0xffffffffu, v, j);
    bool lower = ((i & j) == 0);
    bool desc  = ((i & k) == 0);
    bool keepMax = (lower == desc);
    bool gt = v > o;
    v = (keepMax == gt) ? v : o;
}
__device__ __forceinline__ void mstep(ull &v, int i, int j) {
    ull o = __shfl_xor_sync(0xffffffffu, v, j);
    bool keepMax = ((i & j) == 0);
    bool gt = v > o;
    v = (keepMax == gt) ? v : o;
}

__global__ __launch_bounds__(256)
void topk_kernel()
{
    const int t  = blockIdx.x;
    const int bh = blockIdx.y;
    const int r  = blockIdx.z;
    const float* Qv = g_Q + (bh * T_ + t) * D_;
    const float* K  = (r == 0 ? g_K0 : g_K1) + bh * T_ * D_;

    __shared__ ull keys[T_];

    const int tid  = threadIdx.x;
    const int lane = tid & 31;
    const int warp = tid >> 5;

    keys[tid]       = 0ull;
    keys[tid + 256] = 0ull;
    float2 q2 = ((const float2*)Qv)[lane];
    __syncthreads();

    // dots: warp-per-source, coalesced
    for (int s = warp; s <= t; s += 8) {
        float2 k2 = ((const float2*)(K + s * D_))[lane];
        float v = q2.x * k2.x + q2.y * k2.y;
        #pragma unroll
        for (int o = 16; o > 0; o >>= 1) v += __shfl_down_sync(0xffffffffu, v, o);
        if (lane == 0) {
            unsigned u = __float_as_uint(v);
            u ^= (u & 0x80000000u) ? 0xFFFFFFFFu : 0x80000000u;
            keys[s] = ((ull)u << 32) | (unsigned)(~(unsigned)s);
        }
    }
    __syncthreads();

    // each warp sorts its 64 keys in registers (descending)
    ull r0 = keys[warp * 64 + lane];
    ull r1 = keys[warp * 64 + 32 + lane];
    #pragma unroll
    for (int k = 2; k <= 64; k <<= 1) {
        #pragma unroll
        for (int j = k >> 1; j > 0; j >>= 1) {
            if (j == 32) {
                ull hi = r0 > r1 ? r0 : r1;
                ull lo = r0 > r1 ? r1 : r0;
                r0 = hi; r1 = lo;
            } else {
                cex(r0, lane,      j, k);
                cex(r1, lane + 32, j, k);
            }
        }
    }

    // 3 merge rounds: keep top-64 of pair, all warps converge to same list
    #pragma unroll
    for (int s = 1; s <= 4; s <<= 1) {
        keys[warp * 64 + lane]      = r0;
        keys[warp * 64 + 32 + lane] = r1;
        __syncthreads();
        int p = warp ^ s;
        ull o0 = keys[p * 64 + 63 - lane];
        ull o1 = keys[p * 64 + 31 - lane];
        r0 = r0 > o0 ? r0 : o0;
        r1 = r1 > o1 ? r1 : o1;
        ull hi = r0 > r1 ? r0 : r1;
        ull lo = r0 > r1 ? r1 : r0;
        r0 = hi; r1 = lo;
        #pragma unroll
        for (int j = 16; j > 0; j >>= 1) {
            mstep(r0, lane,      j);
            mstep(r1, lane + 32, j);
        }
        __syncthreads();
    }

    if (warp == 0) {
        keys[lane]      = r0;
        keys[32 + lane] = r1;
        __syncwarp();
        int* dst = (r == 0 ? g_idx0 : g_idx1) + (bh * T_ + t) * KK_;
        int rk0 = min(lane, t);
        int rk1 = min(lane + 32, t);
        dst[lane]      = (int)(~(unsigned)(keys[rk0] & 0xffffffffull));
        dst[lane + 32] = (int)(~(unsigned)(keys[rk1] & 0xffffffffull));
    }
}

// ---------------------------------------------------------------------------
// 3) Order-3 attention per (b,h,t).  grid (T,BH), 64 threads, 8x8 micro
// ---------------------------------------------------------------------------
#define PAD 65
#define ATT_SMEM ((3 * 64 * PAD + 64) * 4 + 2 * 64 * 4)

__global__ __launch_bounds__(64)
void attn_kernel()
{
    extern __shared__ float sm[];
    float* buf1 = sm;                      // P0 -> later W
    float* buf2 = sm + 64 * PAD;           // K1g -> later V1g
    float* buf3 = sm + 2 * 64 * PAD;       // A / exp(A)
    float* qs   = sm + 3 * 64 * PAD;       // q, later row inv-sums
    int*   si0  = (int*)(qs + 64);
    int*   si1  = si0 + 64;

    const int t  = blockIdx.x;
    const int bh = blockIdx.y;
    const int tid = threadIdx.x;
    const int tx = tid & 7, ty = tid >> 3;

    const float* K0b = g_K0 + bh * T_ * D_;
    const float* K1b = g_K1 + bh * T_ * D_;
    const float* V0b = g_V0 + bh * T_ * D_;
    const float* V1b = g_V1 + bh * T_ * D_;

    qs[tid]  = g_Q[(bh * T_ + t) * D_ + tid];
    si0[tid] = g_idx0[(bh * T_ + t) * KK_ + tid];
    si1[tid] = g_idx1[(bh * T_ + t) * KK_ + tid];
    __syncthreads();

    // gather: P0[j][d] = q[d]*K0g, K1g
    #pragma unroll
    for (int it = 0; it < 16; it++) {
        int i4 = tid + it * 64;
        int j = i4 >> 4, c = (i4 & 15) << 2;
        float4 v0 = *(const float4*)(K0b + si0[j] * D_ + c);
        buf1[j * PAD + c + 0] = qs[c + 0] * v0.x;
        buf1[j * PAD + c + 1] = qs[c + 1] * v0.y;
        buf1[j * PAD + c + 2] = qs[c + 2] * v0.z;
        buf1[j * PAD + c + 3] = qs[c + 3] * v0.w;
        float4 v1 = *(const float4*)(K1b + si1[j] * D_ + c);
        buf2[j * PAD + c + 0] = v1.x;
        buf2[j * PAD + c + 1] = v1.y;
        buf2[j * PAD + c + 2] = v1.z;
        buf2[j * PAD + c + 3] = v1.w;
    }
    __syncthreads();

    // A = P0 @ K1g^T * scale   (contraction over d)
    {
        float acc[8][8];
        #pragma unroll
        for (int i = 0; i < 8; i++)
            #pragma unroll
            for (int j = 0; j < 8; j++) acc[i][j] = 0.f;
        #pragma unroll 4
        for (int d = 0; d < 64; d++) {
            float a[8], b[8];
            #pragma unroll
            for (int i = 0; i < 8; i++) a[i] = buf1[(ty * 8 + i) * PAD + d];
            #pragma unroll
            for (int j = 0; j < 8; j++) b[j] = buf2[(tx * 8 + j) * PAD + d];
            #pragma unroll
            for (int i = 0; i < 8; i++)
                #pragma unroll
                for (int j = 0; j < 8; j++) acc[i][j] += a[i] * b[j];
        }
        #pragma unroll
        for (int i = 0; i < 8; i++)
            #pragma unroll
            for (int j = 0; j < 8; j++)
                buf3[(ty * 8 + i) * PAD + tx * 8 + j] = acc[i][j] * 0.125f;
    }
    __syncthreads();

    // softmax: thread-per-row, store exp unnormalized + inv-sum in qs[row]
    {
        int row = tid;
        float m = -1e30f;
        #pragma unroll 8
        for (int k = 0; k < 64; k++) m = fmaxf(m, buf3[row * PAD + k]);
        float s = 0.f;
        #pragma unroll 8
        for (int k = 0; k < 64; k++) {
            float e = __expf(buf3[row * PAD + k] - m);
            buf3[row * PAD + k] = e;
            s += e;
        }
        qs[row] = __frcp_rn(s);
    }

    // gather V1g into buf2 (K1g dead; matmul1 reads done at last barrier)
    #pragma unroll
    for (int it = 0; it < 16; it++) {
        int i4 = tid + it * 64;
        int j = i4 >> 4, c = (i4 & 15) << 2;
        float4 v1 = *(const float4*)(V1b + si1[j] * D_ + c);
        buf2[j * PAD + c + 0] = v1.x;
        buf2[j * PAD + c + 1] = v1.y;
        buf2[j * PAD + c + 2] = v1.z;
        buf2[j * PAD + c + 3] = v1.w;
    }
    __syncthreads();

    // W = exp(A) @ V1g, rows scaled by inv-sum  -> buf1
    {
        float acc[8][8];
        #pragma unroll
        for (int i = 0; i < 8; i++)
            #pragma unroll
            for (int j = 0; j < 8; j++) acc[i][j] = 0.f;
        #pragma unroll 4
        for (int k = 0; k < 64; k++) {
            float a[8], b[8];
            #pragma unroll
            for (int i = 0; i < 8; i++) a[i] = buf3[(ty * 8 + i) * PAD + k];
            #pragma unroll
            for (int j = 0; j < 8; j++) b[j] = buf2[k * PAD + tx * 8 + j];
            #pragma unroll
            for (int i = 0; i < 8; i++)
                #pragma unroll
                for (int j = 0; j < 8; j++) acc[i][j] += a[i] * b[j];
        }
        #pragma unroll
        for (int i = 0; i < 8; i++) {
            float inv = qs[ty * 8 + i];
            #pragma unroll
            for (int j = 0; j < 8; j++)
                buf1[(ty * 8 + i) * PAD + tx * 8 + j] = acc[i][j] * inv;
        }
    }
    __syncthreads();

    // out[d] = sum_j W[j][d] * V0[idx0[j]][d]
    {
        int d = tid;
        float s = 0.f;
        #pragma unroll 8
        for (int j = 0; j < 64; j++)
            s += buf1[j * PAD + d] * V0b[si0[j] * D_ + d];
        int b = bh >> 3, h = bh & 7;
        g_ctx[(b * T_ + t) * HD_ + h * D_ + d] = s;
    }
}

// ---------------------------------------------------------------------------
// 4) out = ctx @ Wo.   64x64 tile, 64 threads, 8x8 micro.  grid (8,16)
// ---------------------------------------------------------------------------
__global__ __launch_bounds__(64)
void out_kernel(const float* __restrict__ Wo, float* __restrict__ out)
{
    const int n0 = blockIdx.x * 64;
    const int m0 = blockIdx.y * 64;
    const int tid = threadIdx.x;
    const int tx = tid & 7, ty = tid >> 3;

    __shared__ float As[16][64];
    __shared__ float Bs[16][64];

    float acc[8][8];
    #pragma unroll
    for (int i = 0; i < 8; i++)
        #pragma unroll
        for (int j = 0; j < 8; j++) acc[i][j] = 0.f;

    for (int k0 = 0; k0 < HD_; k0 += 16) {
        #pragma unroll
        for (int r = 0; r < 4; r++) {
            int idx = tid + r * 64;
            int m = idx >> 2, kp = (idx & 3) * 4;
            float4 v = *(const float4*)(g_ctx + (m0 + m) * HD_ + k0 + kp);
            As[kp + 0][m] = v.x; As[kp + 1][m] = v.y;
            As[kp + 2][m] = v.z; As[kp + 3][m] = v.w;
        }
        #pragma unroll
        for (int r = 0; r < 4; r++) {
            int idx = tid + r * 64;
            int row = idx >> 4, ch = (idx & 15) * 4;
            *(float4*)&Bs[row][ch] =
                *(const float4*)(Wo + (k0 + row) * E_ + n0 + ch);
        }
        __syncthreads();
        #pragma unroll
        for (int kk = 0; kk < 16; kk++) {
            float4 a0 = *(const float4*)&As[kk][ty * 8];
            float4 a1 = *(const float4*)&As[kk][ty * 8 + 4];
            float4 b0 = *(const float4*)&Bs[kk][tx * 8];
            float4 b1 = *(const float4*)&Bs[kk][tx * 8 + 4];
            float a[8] = {a0.x,a0.y,a0.z,a0.w,a1.x,a1.y,a1.z,a1.w};
            float b[8] = {b0.x,b0.y,b0.z,b0.w,b1.x,b1.y,b1.z,b1.w};
            #pragma unroll
            for (int i = 0; i < 8; i++)
                #pragma unroll
                for (int j = 0; j < 8; j++) acc[i][j] += a[i] * b[j];
        }
        __syncthreads();
    }
    #pragma unroll
    for (int i = 0; i < 8; i++) {
        float* crow = out + (m0 + ty * 8 + i) * E_ + n0 + tx * 8;
        #pragma unroll
        for (int j = 0; j < 8; j++) crow[j] = acc[i][j];
    }
}

// ---------------------------------------------------------------------------
extern "C" void kernel_launch(void* const* d_in, const int* in_sizes, int n_in,
                              void* d_out, int out_size)
{
    const float* x  = (const float*)d_in[0];
    const float* Wq = (const float*)d_in[1];
    const float* Wk = (const float*)d_in[2];
    const float* Wv = (const float*)d_in[3];
    const float* Wo = (const float*)d_in[4];
    float* out = (float*)d_out;

    cudaFuncSetAttribute(attn_kernel,
                         cudaFuncAttributeMaxDynamicSharedMemorySize, ATT_SMEM);

    dim3 gProj(40, 16);
    proj_kernel<<<gProj, 64>>>(x, Wq, Wk, Wv);

    dim3 gTop(T_, BH_, 2);
    topk_kernel<<<gTop, 256>>>();

    dim3 gAtt(T_, BH_);
    attn_kernel<<<gAtt, 64, ATT_SMEM>>>();

    dim3 gOut(E_ / 64, M_ / 64);
    out_kernel<<<gOut, 64>>>(Wo, out);
}

// round 3
// speedup vs baseline: 1.4947x; 1.1622x over previous
#include <cuda_runtime.h>
#include <math.h>

#define B_  2
#define T_  512
#define H_  8
#define D_  64
#define E_  512
#define HD_ 512
#define BH_ 16
#define KK_ 64
#define M_  1024

typedef unsigned long long ull;

// ---------------- scratch ----------------
__device__ float g_Q [BH_ * T_ * D_];
__device__ float g_K0[BH_ * T_ * D_];
__device__ float g_K1[BH_ * T_ * D_];
__device__ float g_V0[BH_ * T_ * D_];
__device__ float g_V1[BH_ * T_ * D_];
__device__ float g_ctx[M_ * HD_];
__device__ int   g_idx0[BH_ * T_ * KK_];
__device__ int   g_idx1[BH_ * T_ * KK_];

// ---------------------------------------------------------------------------
// 1) Projections: 128x128 tile, 256 thr, 8x8 micro (split fragments), BK=8,
//    register prefetch.  grid (20, 8)
// ---------------------------------------------------------------------------
#define ASTR 132
__global__ __launch_bounds__(256)
void proj_kernel(const float* __restrict__ x,
                 const float* __restrict__ Wq,
                 const float* __restrict__ Wk,
                 const float* __restrict__ Wv)
{
    const int bx = blockIdx.x;           // 0..19
    const int z  = bx >> 2;
    const int nb = (bx & 3) * 128;       // n offset within matrix
    const int m0 = blockIdx.y * 128;

    const float* Bm = (z == 0) ? Wq
                    : (z <= 2) ? (Wk + (z - 1) * (E_ * HD_))
                               : (Wv + (z - 3) * (E_ * HD_));
    float* C = (z == 0) ? g_Q : (z == 1) ? g_K0 : (z == 2) ? g_K1
             : (z == 3) ? g_V0 : g_V1;

    const int tid = threadIdx.x;
    const int tx = tid & 15, ty = tid >> 4;

    __shared__ float As[8][ASTR];   // [k][m] transposed
    __shared__ float Bs[8][128];    // [k][n]

    // loader indices
    const int am = tid >> 1, akp = (tid & 1) * 4;      // A: 2 thr/row, 8 k
    const int brow = tid >> 5, bch = (tid & 31) * 4;   // B: 8 rows x 128

    float acc[8][8];
    #pragma unroll
    for (int i = 0; i < 8; i++)
        #pragma unroll
        for (int j = 0; j < 8; j++) acc[i][j] = 0.f;

    float4 ra = *(const float4*)(x + (m0 + am) * E_ + akp);
    float4 rb = *(const float4*)(Bm + brow * HD_ + nb + bch);

    for (int k0 = 0; k0 < E_; k0 += 8) {
        As[akp + 0][am] = ra.x; As[akp + 1][am] = ra.y;
        As[akp + 2][am] = ra.z; As[akp + 3][am] = ra.w;
        *(float4*)&Bs[brow][bch] = rb;
        __syncthreads();
        if (k0 + 8 < E_) {
            ra = *(const float4*)(x + (m0 + am) * E_ + k0 + 8 + akp);
            rb = *(const float4*)(Bm + (k0 + 8 + brow) * HD_ + nb + bch);
        }
        #pragma unroll
        for (int kk = 0; kk < 8; kk++) {
            float4 a0 = *(const float4*)&As[kk][ty * 4];
            float4 a1 = *(const float4*)&As[kk][64 + ty * 4];
            float4 b0 = *(const float4*)&Bs[kk][tx * 4];
            float4 b1 = *(const float4*)&Bs[kk][64 + tx * 4];
            float a[8] = {a0.x,a0.y,a0.z,a0.w,a1.x,a1.y,a1.z,a1.w};
            float b[8] = {b0.x,b0.y,b0.z,b0.w,b1.x,b1.y,b1.z,b1.w};
            #pragma unroll
            for (int i = 0; i < 8; i++)
                #pragma unroll
                for (int j = 0; j < 8; j++) acc[i][j] += a[i] * b[j];
        }
        __syncthreads();
    }

    // write head-split
    #pragma unroll
    for (int fi = 0; fi < 2; fi++)
        #pragma unroll
        for (int i = 0; i < 4; i++) {
            int m = m0 + fi * 64 + ty * 4 + i;
            int b = m >> 9, t = m & 511;
            #pragma unroll
            for (int fj = 0; fj < 2; fj++) {
                int nloc = nb + fj * 64 + tx * 4;
                int h = nloc >> 6, d = nloc & 63;
                float4 v = make_float4(acc[fi*4+i][fj*4+0], acc[fi*4+i][fj*4+1],
                                       acc[fi*4+i][fj*4+2], acc[fi*4+i][fj*4+3]);
                *(float4*)(C + (((b << 3) + h) * T_ + t) * D_ + d) = v;
            }
        }
}

// ---------------------------------------------------------------------------
// 2) Causal top-64: warp-register bitonic.  grid (T,BH,2), block 256
// ---------------------------------------------------------------------------
__device__ __forceinline__ void cex(ull &v, int i, int j, int k) {
    ull o = __shfl_xor_sync(0xffffffffu, v, j);
    bool lower = ((i & j) == 0);
    bool desc  = ((i & k) == 0);
    bool keepMax = (lower == desc);
    bool gt = v > o;
    v = (keepMax == gt) ? v : o;
}
__device__ __forceinline__ void mstep(ull &v, int i, int j) {
    ull o = __shfl_xor_sync(0xffffffffu, v, j);
    bool keepMax = ((i & j) == 0);
    bool gt = v > o;
    v = (keepMax == gt) ? v : o;
}

__global__ __launch_bounds__(256)
void topk_kernel()
{
    const int t  = blockIdx.x;
    const int bh = blockIdx.y;
    const int r  = blockIdx.z;
    const float* Qv = g_Q + (bh * T_ + t) * D_;
    const float* K  = (r == 0 ? g_K0 : g_K1) + bh * T_ * D_;

    __shared__ ull keys[T_];

    const int tid  = threadIdx.x;
    const int lane = tid & 31;
    const int warp = tid >> 5;

    keys[tid]       = 0ull;
    keys[tid + 256] = 0ull;
    float2 q2 = ((const float2*)Qv)[lane];
    __syncthreads();

    for (int s = warp; s <= t; s += 8) {
        float2 k2 = ((const float2*)(K + s * D_))[lane];
        float v = q2.x * k2.x + q2.y * k2.y;
        #pragma unroll
        for (int o = 16; o > 0; o >>= 1) v += __shfl_down_sync(0xffffffffu, v, o);
        if (lane == 0) {
            unsigned u = __float_as_uint(v);
            u ^= (u & 0x80000000u) ? 0xFFFFFFFFu : 0x80000000u;
            keys[s] = ((ull)u << 32) | (unsigned)(~(unsigned)s);
        }
    }
    __syncthreads();

    ull r0 = keys[warp * 64 + lane];
    ull r1 = keys[warp * 64 + 32 + lane];
    #pragma unroll
    for (int k = 2; k <= 64; k <<= 1) {
        #pragma unroll
        for (int j = k >> 1; j > 0; j >>= 1) {
            if (j == 32) {
                ull hi = r0 > r1 ? r0 : r1;
                ull lo = r0 > r1 ? r1 : r0;
                r0 = hi; r1 = lo;
            } else {
                cex(r0, lane,      j, k);
                cex(r1, lane + 32, j, k);
            }
        }
    }

    #pragma unroll
    for (int s = 1; s <= 4; s <<= 1) {
        keys[warp * 64 + lane]      = r0;
        keys[warp * 64 + 32 + lane] = r1;
        __syncthreads();
        int p = warp ^ s;
        ull o0 = keys[p * 64 + 63 - lane];
        ull o1 = keys[p * 64 + 31 - lane];
        r0 = r0 > o0 ? r0 : o0;
        r1 = r1 > o1 ? r1 : o1;
        ull hi = r0 > r1 ? r0 : r1;
        ull lo = r0 > r1 ? r1 : r0;
        r0 = hi; r1 = lo;
        #pragma unroll
        for (int j = 16; j > 0; j >>= 1) {
            mstep(r0, lane,      j);
            mstep(r1, lane + 32, j);
        }
        __syncthreads();
    }

    if (warp == 0) {
        keys[lane]      = r0;
        keys[32 + lane] = r1;
        __syncwarp();
        int* dst = (r == 0 ? g_idx0 : g_idx1) + (bh * T_ + t) * KK_;
        int rk0 = min(lane, t);
        int rk1 = min(lane + 32, t);
        dst[lane]      = (int)(~(unsigned)(keys[rk0] & 0xffffffffull));
        dst[lane + 32] = (int)(~(unsigned)(keys[rk1] & 0xffffffffull));
    }
}

// ---------------------------------------------------------------------------
// 3) Order-3 attention.  grid (T,BH), 128 threads, 4x8 micro, f4 fragments.
// ---------------------------------------------------------------------------
#define PAD3 65    // A buffer stride (scalar access only)
#define TRS  68    // f4-aligned stride for transposed / row-major buffers
#define ATT_SMEM ((2 * 64 * TRS + 64 * PAD3 + 64 + 128) * 4 + 2 * 64 * 4)

__global__ __launch_bounds__(128)
void attn_kernel()
{
    extern __shared__ float sm[];
    float* buf1 = sm;                       // P0^T [d][j] -> later V1g [k][d]
    float* buf2 = sm + 64 * TRS;            // K1^T [d][k] -> later W [j][d]
    float* buf3 = sm + 2 * 64 * TRS;        // A / exp(A)   [j][k]
    float* qs   = sm + 2 * 64 * TRS + 64 * PAD3;  // q, then row inv-sums
    float* part = qs + 64;                  // 128
    int*   si0  = (int*)(part + 128);
    int*   si1  = si0 + 64;

    const int t  = blockIdx.x;
    const int bh = blockIdx.y;
    const int tid = threadIdx.x;
    const int tx = tid & 7, ty = tid >> 3;

    const float* K0b = g_K0 + bh * T_ * D_;
    const float* K1b = g_K1 + bh * T_ * D_;
    const float* V0b = g_V0 + bh * T_ * D_;
    const float* V1b = g_V1 + bh * T_ * D_;

    if (tid < 64) {
        qs[tid]  = g_Q[(bh * T_ + t) * D_ + tid];
        si0[tid] = g_idx0[(bh * T_ + t) * KK_ + tid];
        si1[tid] = g_idx1[(bh * T_ + t) * KK_ + tid];
    }
    __syncthreads();

    // gather transposed: buf1[d][j] = q[d]*K0g[j][d] ; buf2[d][k] = K1g[k][d]
    #pragma unroll
    for (int it = 0; it < 8; it++) {
        int i4 = tid + it * 128;
        int j = i4 >> 4, c = (i4 & 15) << 2;
        float4 v0 = *(const float4*)(K0b + si0[j] * D_ + c);
        buf1[(c + 0) * TRS + j] = qs[c + 0] * v0.x;
        buf1[(c + 1) * TRS + j] = qs[c + 1] * v0.y;
        buf1[(c + 2) * TRS + j] = qs[c + 2] * v0.z;
        buf1[(c + 3) * TRS + j] = qs[c + 3] * v0.w;
        float4 v1 = *(const float4*)(K1b + si1[j] * D_ + c);
        buf2[(c + 0) * TRS + j] = v1.x;
        buf2[(c + 1) * TRS + j] = v1.y;
        buf2[(c + 2) * TRS + j] = v1.z;
        buf2[(c + 3) * TRS + j] = v1.w;
    }
    __syncthreads();

    // A[j][k] = sum_d P0T[d][j] * K1T[d][k], * scale
    {
        float acc[4][8];
        #pragma unroll
        for (int i = 0; i < 4; i++)
            #pragma unroll
            for (int j = 0; j < 8; j++) acc[i][j] = 0.f;
        #pragma unroll 4
        for (int d = 0; d < 64; d++) {
            float4 av = *(const float4*)&buf1[d * TRS + ty * 4];
            float4 b0 = *(const float4*)&buf2[d * TRS + tx * 4];
            float4 b1 = *(const float4*)&buf2[d * TRS + 32 + tx * 4];
            float a[4] = {av.x, av.y, av.z, av.w};
            float b[8] = {b0.x,b0.y,b0.z,b0.w,b1.x,b1.y,b1.z,b1.w};
            #pragma unroll
            for (int i = 0; i < 4; i++)
                #pragma unroll
                for (int j = 0; j < 8; j++) acc[i][j] += a[i] * b[j];
        }
        #pragma unroll
        for (int i = 0; i < 4; i++) {
            int row = ty * 4 + i;
            #pragma unroll
            for (int j = 0; j < 4; j++) {
                buf3[row * PAD3 + tx * 4 + j]      = acc[i][j]     * 0.125f;
                buf3[row * PAD3 + 32 + tx * 4 + j] = acc[i][4 + j] * 0.125f;
            }
        }
    }
    __syncthreads();

    // softmax (thread-per-row, unnormalized exp + inv-sum); others load V1g
    if (tid < 64) {
        int row = tid;
        float m = -1e30f;
        #pragma unroll 8
        for (int k = 0; k < 64; k++) m = fmaxf(m, buf3[row * PAD3 + k]);
        float s = 0.f;
        #pragma unroll 8
        for (int k = 0; k < 64; k++) {
            float e = __expf(buf3[row * PAD3 + k] - m);
            buf3[row * PAD3 + k] = e;
            s += e;
        }
        qs[row] = __frcp_rn(s);
    }
    // V1g into buf1 [k][d] (buf1 free after matmul1 barrier)
    #pragma unroll
    for (int it = 0; it < 8; it++) {
        int i4 = tid + it * 128;
        int k = i4 >> 4, c = (i4 & 15) << 2;
        *(float4*)&buf1[k * TRS + c] = *(const float4*)(V1b + si1[k] * D_ + c);
    }
    __syncthreads();

    // W[j][d] = inv[j] * sum_k exp(A)[j][k] * V1g[k][d]  -> buf2
    {
        float acc[4][8];
        #pragma unroll
        for (int i = 0; i < 4; i++)
            #pragma unroll
            for (int j = 0; j < 8; j++) acc[i][j] = 0.f;
        #pragma unroll 4
        for (int k = 0; k < 64; k++) {
            float a[4];
            #pragma unroll
            for (int i = 0; i < 4; i++) a[i] = buf3[(ty * 4 + i) * PAD3 + k];
            float4 b0 = *(const float4*)&buf1[k * TRS + tx * 4];
            float4 b1 = *(const float4*)&buf1[k * TRS + 32 + tx * 4];
            float b[8] = {b0.x,b0.y,b0.z,b0.w,b1.x,b1.y,b1.z,b1.w};
            #pragma unroll
            for (int i = 0; i < 4; i++)
                #pragma unroll
                for (int j = 0; j < 8; j++) acc[i][j] += a[i] * b[j];
        }
        #pragma unroll
        for (int i = 0; i < 4; i++) {
            int row = ty * 4 + i;
            float inv = qs[row];
            float4 w0 = make_float4(acc[i][0]*inv, acc[i][1]*inv,
                                    acc[i][2]*inv, acc[i][3]*inv);
            float4 w1 = make_float4(acc[i][4]*inv, acc[i][5]*inv,
                                    acc[i][6]*inv, acc[i][7]*inv);
            *(float4*)&buf2[row * TRS + tx * 4]      = w0;
            *(float4*)&buf2[row * TRS + 32 + tx * 4] = w1;
        }
    }
    __syncthreads();

    // out[d] = sum_j W[j][d] * V0g[j][d]
    {
        int d  = tid & 63;
        int jg = tid >> 6;                    // 0,1
        float s = 0.f;
        #pragma unroll 8
        for (int jj = 0; jj < 32; jj++) {
            int j = jg * 32 + jj;
            s += buf2[j * TRS + d] * V0b[si0[j] * D_ + d];
        }
        part[jg * 64 + d] = s;
        __syncthreads();
        if (tid < 64) {
            float o = part[tid] + part[64 + tid];
            int b = bh >> 3, h = bh & 7;
            g_ctx[(b * T_ + t) * HD_ + h * D_ + tid] = o;
        }
    }
}

// ---------------------------------------------------------------------------
// 4) out = ctx @ Wo.  64x64 tile, 256 thr, 4x4 micro, BK=16, prefetch.
//    grid (8, 16)
// ---------------------------------------------------------------------------
#define OASTR 68
__global__ __launch_bounds__(256)
void out_kernel(const float* __restrict__ Wo, float* __restrict__ out)
{
    const int n0 = blockIdx.x * 64;
    const int m0 = blockIdx.y * 64;
    const int tid = threadIdx.x;
    const int tx = tid & 15, ty = tid >> 4;

    __shared__ float As[16][OASTR];   // [k][m]
    __shared__ float Bs[16][64];      // [k][n]

    const int am = tid >> 2, akp = (tid & 3) * 4;     // A: 4 thr/row, 16 k
    const int brow = tid >> 4, bch = (tid & 15) * 4;  // B: 16 rows x 64

    float acc[4][4];
    #pragma unroll
    for (int i = 0; i < 4; i++)
        #pragma unroll
        for (int j = 0; j < 4; j++) acc[i][j] = 0.f;

    float4 ra = *(const float4*)(g_ctx + (m0 + am) * HD_ + akp);
    float4 rb = *(const float4*)(Wo + brow * E_ + n0 + bch);

    for (int k0 = 0; k0 < HD_; k0 += 16) {
        As[akp + 0][am] = ra.x; As[akp + 1][am] = ra.y;
        As[akp + 2][am] = ra.z; As[akp + 3][am] = ra.w;
        *(float4*)&Bs[brow][bch] = rb;
        __syncthreads();
        if (k0 + 16 < HD_) {
            ra = *(const float4*)(g_ctx + (m0 + am) * HD_ + k0 + 16 + akp);
            rb = *(const float4*)(Wo + (k0 + 16 + brow) * E_ + n0 + bch);
        }
        #pragma unroll
        for (int kk = 0; kk < 16; kk++) {
            float4 av = *(const float4*)&As[kk][ty * 4];
            float4 bv = *(const float4*)&Bs[kk][tx * 4];
            float a[4] = {av.x, av.y, av.z, av.w};
            float b[4] = {bv.x, bv.y, bv.z, bv.w};
            #pragma unroll
            for (int i = 0; i < 4; i++)
                #pragma unroll
                for (int j = 0; j < 4; j++) acc[i][j] += a[i] * b[j];
        }
        __syncthreads();
    }
    #pragma unroll
    for (int i = 0; i < 4; i++) {
        float4 v = make_float4(acc[i][0], acc[i][1], acc[i][2], acc[i][3]);
        *(float4*)(out + (m0 + ty * 4 + i) * E_ + n0 + tx * 4) = v;
    }
}

// ---------------------------------------------------------------------------
extern "C" void kernel_launch(void* const* d_in, const int* in_sizes, int n_in,
                              void* d_out, int out_size)
{
    const float* x  = (const float*)d_in[0];
    const float* Wq = (const float*)d_in[1];
    const float* Wk = (const float*)d_in[2];
    const float* Wv = (const float*)d_in[3];
    const float* Wo = (const float*)d_in[4];
    float* out = (float*)d_out;

    cudaFuncSetAttribute(attn_kernel,
                         cudaFuncAttributeMaxDynamicSharedMemorySize, ATT_SMEM);

    dim3 gProj(20, 8);
    proj_kernel<<<gProj, 256>>>(x, Wq, Wk, Wv);

    dim3 gTop(T_, BH_, 2);
    topk_kernel<<<gTop, 256>>>();

    dim3 gAtt(T_, BH_);
    attn_kernel<<<gAtt, 128, ATT_SMEM>>>();

    dim3 gOut(E_ / 64, M_ / 64);
    out_kernel<<<gOut, 256>>>(Wo, out);
}

// round 5
// speedup vs baseline: 1.6676x; 1.1156x over previous
#include <cuda_runtime.h>
#include <math.h>

#define B_  2
#define T_  512
#define H_  8
#define D_  64
#define E_  512
#define HD_ 512
#define BH_ 16
#define KK_ 64
#define M_  1024

typedef unsigned long long ull;

// ---------------- scratch ----------------
__device__ float g_Q [BH_ * T_ * D_];
__device__ float g_K0[BH_ * T_ * D_];
__device__ float g_K1[BH_ * T_ * D_];
__device__ float g_V0[BH_ * T_ * D_];
__device__ float g_V1[BH_ * T_ * D_];
__device__ float g_ctx[M_ * HD_];
__device__ int   g_idx0[BH_ * T_ * KK_];
__device__ int   g_idx1[BH_ * T_ * KK_];

// ---------------------------------------------------------------------------
// 1) Projections: 128x128 tile, 256 thr, 8x8 micro, BK=8, prefetch. grid(20,8)
// ---------------------------------------------------------------------------
#define ASTR 132
__global__ __launch_bounds__(256)
void proj_kernel(const float* __restrict__ x,
                 const float* __restrict__ Wq,
                 const float* __restrict__ Wk,
                 const float* __restrict__ Wv)
{
    const int bx = blockIdx.x;
    const int z  = bx >> 2;
    const int nb = (bx & 3) * 128;
    const int m0 = blockIdx.y * 128;

    const float* Bm = (z == 0) ? Wq
                    : (z <= 2) ? (Wk + (z - 1) * (E_ * HD_))
                               : (Wv + (z - 3) * (E_ * HD_));
    float* C = (z == 0) ? g_Q : (z == 1) ? g_K0 : (z == 2) ? g_K1
             : (z == 3) ? g_V0 : g_V1;

    const int tid = threadIdx.x;
    const int tx = tid & 15, ty = tid >> 4;

    __shared__ float As[8][ASTR];
    __shared__ float Bs[8][128];

    const int am = tid >> 1, akp = (tid & 1) * 4;
    const int brow = tid >> 5, bch = (tid & 31) * 4;

    float acc[8][8];
    #pragma unroll
    for (int i = 0; i < 8; i++)
        #pragma unroll
        for (int j = 0; j < 8; j++) acc[i][j] = 0.f;

    float4 ra = *(const float4*)(x + (m0 + am) * E_ + akp);
    float4 rb = *(const float4*)(Bm + brow * HD_ + nb + bch);

    for (int k0 = 0; k0 < E_; k0 += 8) {
        As[akp + 0][am] = ra.x; As[akp + 1][am] = ra.y;
        As[akp + 2][am] = ra.z; As[akp + 3][am] = ra.w;
        *(float4*)&Bs[brow][bch] = rb;
        __syncthreads();
        if (k0 + 8 < E_) {
            ra = *(const float4*)(x + (m0 + am) * E_ + k0 + 8 + akp);
            rb = *(const float4*)(Bm + (k0 + 8 + brow) * HD_ + nb + bch);
        }
        #pragma unroll
        for (int kk = 0; kk < 8; kk++) {
            float4 a0 = *(const float4*)&As[kk][ty * 4];
            float4 a1 = *(const float4*)&As[kk][64 + ty * 4];
            float4 b0 = *(const float4*)&Bs[kk][tx * 4];
            float4 b1 = *(const float4*)&Bs[kk][64 + tx * 4];
            float a[8] = {a0.x,a0.y,a0.z,a0.w,a1.x,a1.y,a1.z,a1.w};
            float b[8] = {b0.x,b0.y,b0.z,b0.w,b1.x,b1.y,b1.z,b1.w};
            #pragma unroll
            for (int i = 0; i < 8; i++)
                #pragma unroll
                for (int j = 0; j < 8; j++) acc[i][j] += a[i] * b[j];
        }
        __syncthreads();
    }

    #pragma unroll
    for (int fi = 0; fi < 2; fi++)
        #pragma unroll
        for (int i = 0; i < 4; i++) {
            int m = m0 + fi * 64 + ty * 4 + i;
            int b = m >> 9, t = m & 511;
            #pragma unroll
            for (int fj = 0; fj < 2; fj++) {
                int nloc = nb + fj * 64 + tx * 4;
                int h = nloc >> 6, d = nloc & 63;
                float4 v = make_float4(acc[fi*4+i][fj*4+0], acc[fi*4+i][fj*4+1],
                                       acc[fi*4+i][fj*4+2], acc[fi*4+i][fj*4+3]);
                *(float4*)(C + (((b << 3) + h) * T_ + t) * D_ + d) = v;
            }
        }
}

// ---------------------------------------------------------------------------
// 2) Causal top-64: warp-register bitonic.  grid (T,BH,2), block 256
// ---------------------------------------------------------------------------
__device__ __forceinline__ void cex(ull &v, int i, int j, int k) {
    ull o = __shfl_xor_sync(0xffffffffu, v, j);
    bool lower = ((i & j) == 0);
    bool desc  = ((i & k) == 0);
    bool keepMax = (lower == desc);
    bool gt = v > o;
    v = (keepMax == gt) ? v : o;
}
__device__ __forceinline__ void mstep(ull &v, int i, int j) {
    ull o = __shfl_xor_sync(0xffffffffu, v, j);
    bool keepMax = ((i & j) == 0);
    bool gt = v > o;
    v = (keepMax == gt) ? v : o;
}

__global__ __launch_bounds__(256)
void topk_kernel()
{
    const int t  = blockIdx.x;
    const int bh = blockIdx.y;
    const int r  = blockIdx.z;
    const float* Qv = g_Q + (bh * T_ + t) * D_;
    const float* K  = (r == 0 ? g_K0 : g_K1) + bh * T_ * D_;

    __shared__ ull keys[T_];

    const int tid  = threadIdx.x;
    const int lane = tid & 31;
    const int warp = tid >> 5;

    keys[tid]       = 0ull;
    keys[tid + 256] = 0ull;
    float2 q2 = ((const float2*)Qv)[lane];
    __syncthreads();

    for (int s = warp; s <= t; s += 8) {
        float2 k2 = ((const float2*)(K + s * D_))[lane];
        float v = q2.x * k2.x + q2.y * k2.y;
        #pragma unroll
        for (int o = 16; o > 0; o >>= 1) v += __shfl_down_sync(0xffffffffu, v, o);
        if (lane == 0) {
            unsigned u = __float_as_uint(v);
            u ^= (u & 0x80000000u) ? 0xFFFFFFFFu : 0x80000000u;
            keys[s] = ((ull)u << 32) | (unsigned)(~(unsigned)s);
        }
    }
    __syncthreads();

    ull r0 = keys[warp * 64 + lane];
    ull r1 = keys[warp * 64 + 32 + lane];
    #pragma unroll
    for (int k = 2; k <= 64; k <<= 1) {
        #pragma unroll
        for (int j = k >> 1; j > 0; j >>= 1) {
            if (j == 32) {
                ull hi = r0 > r1 ? r0 : r1;
                ull lo = r0 > r1 ? r1 : r0;
                r0 = hi; r1 = lo;
            } else {
                cex(r0, lane,      j, k);
                cex(r1, lane + 32, j, k);
            }
        }
    }

    #pragma unroll
    for (int s = 1; s <= 4; s <<= 1) {
        keys[warp * 64 + lane]      = r0;
        keys[warp * 64 + 32 + lane] = r1;
        __syncthreads();
        int p = warp ^ s;
        ull o0 = keys[p * 64 + 63 - lane];
        ull o1 = keys[p * 64 + 31 - lane];
        r0 = r0 > o0 ? r0 : o0;
        r1 = r1 > o1 ? r1 : o1;
        ull hi = r0 > r1 ? r0 : r1;
        ull lo = r0 > r1 ? r1 : r0;
        r0 = hi; r1 = lo;
        #pragma unroll
        for (int j = 16; j > 0; j >>= 1) {
            mstep(r0, lane,      j);
            mstep(r1, lane + 32, j);
        }
        __syncthreads();
    }

    if (warp == 0) {
        keys[lane]      = r0;
        keys[32 + lane] = r1;
        __syncwarp();
        int* dst = (r == 0 ? g_idx0 : g_idx1) + (bh * T_ + t) * KK_;
        int rk0 = min(lane, t);
        int rk1 = min(lane + 32, t);
        dst[lane]      = (int)(~(unsigned)(keys[rk0] & 0xffffffffull));
        dst[lane + 32] = (int)(~(unsigned)(keys[rk1] & 0xffffffffull));
    }
}

// ---------------------------------------------------------------------------
// 3) Order-3 attention, tf32 tensor cores (3-pass split).  grid (T,BH), 128 thr
// ---------------------------------------------------------------------------
#define SA 68   // stride for A-operand buffers (P0, alpha, W, K1g)
#define SB 72   // stride for V1g (B-operand of mm2)
#define ATT_SMEM ((64*SA + 64*SB + 64*SA + 64 + 128) * 4 + 2 * 64 * 4)

__device__ __forceinline__ unsigned f2tf(float x) {
    unsigned r;
    asm("cvt.rna.tf32.f32 %0, %1;" : "=r"(r) : "f"(x));
    return r;
}
__device__ __forceinline__ void mma8(float* c, const unsigned* a,
                                     unsigned b0, unsigned b1) {
    asm("mma.sync.aligned.m16n8k8.row.col.f32.tf32.tf32.f32 "
        "{%0,%1,%2,%3},{%4,%5,%6,%7},{%8,%9},{%0,%1,%2,%3};"
        : "+f"(c[0]), "+f"(c[1]), "+f"(c[2]), "+f"(c[3])
        : "r"(a[0]), "r"(a[1]), "r"(a[2]), "r"(a[3]), "r"(b0), "r"(b1));
}
__device__ __forceinline__ void split2(float x, unsigned &h, unsigned &l) {
    h = f2tf(x);
    l = f2tf(x - __uint_as_float(h));
}

__global__ __launch_bounds__(128)
void attn_kernel()
{
    extern __shared__ float sm[];
    float* buf1 = sm;                         // P0 [j][d] sA -> W [j][d]
    float* buf2 = sm + 64 * SA;               // K1g [k][d] sA -> V1g [k][d] sB
    float* buf3 = sm + 64 * SA + 64 * SB;     // A/alpha [j][k] sA
    float* qs   = sm + 2 * 64 * SA + 64 * SB; // q, later inv-sums
    float* part = qs + 64;                    // 128
    int*   si0  = (int*)(part + 128);
    int*   si1  = si0 + 64;

    const int t  = blockIdx.x;
    const int bh = blockIdx.y;
    const int tid = threadIdx.x;
    const int lane = tid & 31;
    const int warp = tid >> 5;
    const int gi = lane >> 2;       // groupID
    const int ti = lane & 3;        // thread-in-group

    const float* K0b = g_K0 + bh * T_ * D_;
    const float* K1b = g_K1 + bh * T_ * D_;
    const float* V0b = g_V0 + bh * T_ * D_;
    const float* V1b = g_V1 + bh * T_ * D_;

    if (tid < 64) {
        qs[tid]  = g_Q[(bh * T_ + t) * D_ + tid];
        si0[tid] = g_idx0[(bh * T_ + t) * KK_ + tid];
        si1[tid] = g_idx1[(bh * T_ + t) * KK_ + tid];
    }
    __syncthreads();

    // gathers: P0[j][d] = q[d]*K0g[j][d];  K1g[k][d]
    #pragma unroll
    for (int it = 0; it < 8; it++) {
        int i4 = tid + it * 128;
        int j = i4 >> 4, c = (i4 & 15) << 2;
        float4 v0 = *(const float4*)(K0b + si0[j] * D_ + c);
        float4 p = make_float4(qs[c+0]*v0.x, qs[c+1]*v0.y,
                               qs[c+2]*v0.z, qs[c+3]*v0.w);
        *(float4*)&buf1[j * SA + c] = p;
        *(float4*)&buf2[j * SA + c] = *(const float4*)(K1b + si1[j] * D_ + c);
    }
    __syncthreads();

    // mm1: A = P0 (16w rows), B = K1g^T; D[j][kidx]; 3-pass tf32
    const int m0 = warp * 16;
    {
        float acc[8][4];
        #pragma unroll
        for (int n = 0; n < 8; n++)
            #pragma unroll
            for (int i = 0; i < 4; i++) acc[n][i] = 0.f;
        #pragma unroll
        for (int ks = 0; ks < 8; ks++) {
            int k0 = ks * 8;
            float fa0 = buf1[(m0 + gi) * SA + k0 + ti];
            float fa1 = buf1[(m0 + gi + 8) * SA + k0 + ti];
            float fa2 = buf1[(m0 + gi) * SA + k0 + ti + 4];
            float fa3 = buf1[(m0 + gi + 8) * SA + k0 + ti + 4];
            unsigned ah[4], al[4];
            split2(fa0, ah[0], al[0]); split2(fa1, ah[1], al[1]);
            split2(fa2, ah[2], al[2]); split2(fa3, ah[3], al[3]);
            #pragma unroll
            for (int nt = 0; nt < 8; nt++) {
                int n0 = nt * 8;
                float fb0 = buf2[(n0 + gi) * SA + k0 + ti];
                float fb1 = buf2[(n0 + gi) * SA + k0 + ti + 4];
                unsigned bh0, bl0, bh1, bl1;
                split2(fb0, bh0, bl0); split2(fb1, bh1, bl1);
                mma8(acc[nt], ah, bh0, bh1);
                mma8(acc[nt], ah, bl0, bl1);
                mma8(acc[nt], al, bh0, bh1);
            }
        }
        #pragma unroll
        for (int nt = 0; nt < 8; nt++) {
            int r0 = m0 + gi, c0 = nt * 8 + 2 * ti;
            buf3[r0 * SA + c0]           = acc[nt][0] * 0.125f;
            buf3[r0 * SA + c0 + 1]       = acc[nt][1] * 0.125f;
            buf3[(r0 + 8) * SA + c0]     = acc[nt][2] * 0.125f;
            buf3[(r0 + 8) * SA + c0 + 1] = acc[nt][3] * 0.125f;
        }
    }
    __syncthreads();

    // softmax over k: 2 threads per row, unnormalized exp + inv-sum
    {
        int row = tid >> 1;
        int off = (tid & 1) * 32;
        float* rp = buf3 + row * SA + off;
        float m = -1e30f;
        #pragma unroll 8
        for (int k = 0; k < 32; k++) m = fmaxf(m, rp[k]);
        m = fmaxf(m, __shfl_xor_sync(0xffffffffu, m, 1));
        float s = 0.f;
        #pragma unroll 8
        for (int k = 0; k < 32; k++) {
            float e = __expf(rp[k] - m);
            rp[k] = e;
            s += e;
        }
        s += __shfl_xor_sync(0xffffffffu, s, 1);
        if ((tid & 1) == 0) qs[row] = __frcp_rn(s);
    }
    // V1g into buf2 with stride SB (K1 reads done at mm1-end barrier)
    #pragma unroll
    for (int it = 0; it < 8; it++) {
        int i4 = tid + it * 128;
        int k = i4 >> 4, c = (i4 & 15) << 2;
        *(float4*)&buf2[k * SB + c] = *(const float4*)(V1b + si1[k] * D_ + c);
    }
    __syncthreads();

    // mm2: A = exp(A) [j][k], B = V1g [k][d]; W scaled by inv -> buf1
    {
        float acc[8][4];
        #pragma unroll
        for (int n = 0; n < 8; n++)
            #pragma unroll
            for (int i = 0; i < 4; i++) acc[n][i] = 0.f;
        #pragma unroll
        for (int ks = 0; ks < 8; ks++) {
            int k0 = ks * 8;
            float fa0 = buf3[(m0 + gi) * SA + k0 + ti];
            float fa1 = buf3[(m0 + gi + 8) * SA + k0 + ti];
            float fa2 = buf3[(m0 + gi) * SA + k0 + ti + 4];
            float fa3 = buf3[(m0 + gi + 8) * SA + k0 + ti + 4];
            unsigned ah[4], al[4];
            split2(fa0, ah[0], al[0]); split2(fa1, ah[1], al[1]);
            split2(fa2, ah[2], al[2]); split2(fa3, ah[3], al[3]);
            #pragma unroll
            for (int nt = 0; nt < 8; nt++) {
                int n0 = nt * 8;
                float fb0 = buf2[(k0 + ti) * SB + n0 + gi];
                float fb1 = buf2[(k0 + ti + 4) * SB + n0 + gi];
                unsigned bh0, bl0, bh1, bl1;
                split2(fb0, bh0, bl0); split2(fb1, bh1, bl1);
                mma8(acc[nt], ah, bh0, bh1);
                mma8(acc[nt], ah, bl0, bl1);
                mma8(acc[nt], al, bh0, bh1);
            }
        }
        float inv0 = qs[m0 + gi];
        float inv1 = qs[m0 + gi + 8];
        #pragma unroll
        for (int nt = 0; nt < 8; nt++) {
            int r0 = m0 + gi, c0 = nt * 8 + 2 * ti;
            buf1[r0 * SA + c0]           = acc[nt][0] * inv0;
            buf1[r0 * SA + c0 + 1]       = acc[nt][1] * inv0;
            buf1[(r0 + 8) * SA + c0]     = acc[nt][2] * inv1;
            buf1[(r0 + 8) * SA + c0 + 1] = acc[nt][3] * inv1;
        }
    }
    __syncthreads();

    // out[d] = sum_j W[j][d] * V0g[j][d]
    {
        int d  = tid & 63;
        int jg = tid >> 6;
        float s = 0.f;
        #pragma unroll 8
        for (int jj = 0; jj < 32; jj++) {
            int j = jg * 32 + jj;
            s += buf1[j * SA + d] * V0b[si0[j] * D_ + d];
        }
        part[jg * 64 + d] = s;
        __syncthreads();
        if (tid < 64) {
            float o = part[tid] + part[64 + tid];
            int b = bh >> 3, h = bh & 7;
            g_ctx[(b * T_ + t) * HD_ + h * D_ + tid] = o;
        }
    }
}

// ---------------------------------------------------------------------------
// 4) out = ctx @ Wo.  64x64 tile, 256 thr, 4x4 micro, BK=16, prefetch.
// ---------------------------------------------------------------------------
#define OASTR 68
__global__ __launch_bounds__(256)
void out_kernel(const float* __restrict__ Wo, float* __restrict__ out)
{
    const int n0 = blockIdx.x * 64;
    const int m0 = blockIdx.y * 64;
    const int tid = threadIdx.x;
    const int tx = tid & 15, ty = tid >> 4;

    __shared__ float As[16][OASTR];
    __shared__ float Bs[16][64];

    const int am = tid >> 2, akp = (tid & 3) * 4;
    const int brow = tid >> 4, bch = (tid & 15) * 4;

    float acc[4][4];
    #pragma unroll
    for (int i = 0; i < 4; i++)
        #pragma unroll
        for (int j = 0; j < 4; j++) acc[i][j] = 0.f;

    float4 ra = *(const float4*)(g_ctx + (m0 + am) * HD_ + akp);
    float4 rb = *(const float4*)(Wo + brow * E_ + n0 + bch);

    for (int k0 = 0; k0 < HD_; k0 += 16) {
        As[akp + 0][am] = ra.x; As[akp + 1][am] = ra.y;
        As[akp + 2][am] = ra.z; As[akp + 3][am] = ra.w;
        *(float4*)&Bs[brow][bch] = rb;
        __syncthreads();
        if (k0 + 16 < HD_) {
            ra = *(const float4*)(g_ctx + (m0 + am) * HD_ + k0 + 16 + akp);
            rb = *(const float4*)(Wo + (k0 + 16 + brow) * E_ + n0 + bch);
        }
        #pragma unroll
        for (int kk = 0; kk < 16; kk++) {
            float4 av = *(const float4*)&As[kk][ty * 4];
            float4 bv = *(const float4*)&Bs[kk][tx * 4];
            float a[4] = {av.x, av.y, av.z, av.w};
            float b[4] = {bv.x, bv.y, bv.z, bv.w};
            #pragma unroll
            for (int i = 0; i < 4; i++)
                #pragma unroll
                for (int j = 0; j < 4; j++) acc[i][j] += a[i] * b[j];
        }
        __syncthreads();
    }
    #pragma unroll
    for (int i = 0; i < 4; i++) {
        float4 v = make_float4(acc[i][0], acc[i][1], acc[i][2], acc[i][3]);
        *(float4*)(out + (m0 + ty * 4 + i) * E_ + n0 + tx * 4) = v;
    }
}

// ---------------------------------------------------------------------------
extern "C" void kernel_launch(void* const* d_in, const int* in_sizes, int n_in,
                              void* d_out, int out_size)
{
    const float* x  = (const float*)d_in[0];
    const float* Wq = (const float*)d_in[1];
    const float* Wk = (const float*)d_in[2];
    const float* Wv = (const float*)d_in[3];
    const float* Wo = (const float*)d_in[4];
    float* out = (float*)d_out;

    cudaFuncSetAttribute(attn_kernel,
                         cudaFuncAttributeMaxDynamicSharedMemorySize, ATT_SMEM);

    dim3 gProj(20, 8);
    proj_kernel<<<gProj, 256>>>(x, Wq, Wk, Wv);

    dim3 gTop(T_, BH_, 2);
    topk_kernel<<<gTop, 256>>>();

    dim3 gAtt(T_, BH_);
    attn_kernel<<<gAtt, 128, ATT_SMEM>>>();

    dim3 gOut(E_ / 64, M_ / 64);
    out_kernel<<<gOut, 256>>>(Wo, out);
}